// round 8
// baseline (speedup 1.0000x reference)
#include <cuda_runtime.h>
#include <cstdint>

#define DDIM 128
#define MAXN 50048
#define MAXE 2097152

// Scratch (allocation-free: __device__ globals)
__device__ float g_x1 [(size_t)MAXN * DDIM];
__device__ float g_x2 [(size_t)MAXN * DDIM];
__device__ int   g_cnt[MAXN];
__device__ int   g_rowptr[MAXN + 1];
__device__ int   g_cursor[MAXN];
__device__ int   g_esrc[MAXE];

// ---------------------------------------------------------------------------
// Helpers
// ---------------------------------------------------------------------------
__device__ __forceinline__ uint32_t f2tf32(float f) {
    uint32_t r;
    asm("cvt.rna.tf32.f32 %0, %1;" : "=r"(r) : "f"(f));
    return r;
}
__device__ __forceinline__ void mma_m16n8k8(float c[4], const uint32_t a[4],
                                            const uint32_t b[2]) {
    asm volatile(
        "mma.sync.aligned.m16n8k8.row.col.f32.tf32.tf32.f32 "
        "{%0,%1,%2,%3}, {%4,%5,%6,%7}, {%8,%9}, {%0,%1,%2,%3};\n"
        : "+f"(c[0]), "+f"(c[1]), "+f"(c[2]), "+f"(c[3])
        : "r"(a[0]), "r"(a[1]), "r"(a[2]), "r"(a[3]), "r"(b[0]), "r"(b[1]));
}
#define BAR_SYNC(id)   asm volatile("bar.sync %0, 256;"   :: "r"(id) : "memory")
#define BAR_ARRIVE(id) asm volatile("bar.arrive %0, 256;" :: "r"(id) : "memory")

// ---------------------------------------------------------------------------
// Edge dtype self-detection (int64 vs int32)
// ---------------------------------------------------------------------------
__device__ __forceinline__ bool edges_are_i64(const void* ei, int N) {
    const long long* e64 = (const long long*)ei;
#pragma unroll
    for (int i = 0; i < 4; i++) {
        long long v = e64[i];
        if (v < 0 || v >= (long long)N) return false;
    }
    return true;
}

__global__ void zero_cnt_kernel(int* cnt, int n) {
    int i = blockIdx.x * blockDim.x + threadIdx.x;
    if (i < n) cnt[i] = 0;
}

__global__ void hist_kernel(int* cnt, const void* ei, int E, int N) {
    int i = blockIdx.x * blockDim.x + threadIdx.x;
    if (i >= E) return;
    bool is64 = edges_are_i64(ei, N);
    int d;
    if (is64) d = (int)((const long long*)ei)[E + i];
    else      d = ((const int*)ei)[E + i];
    atomicAdd(&cnt[d], 1);
}

__global__ void scan_kernel(const int* __restrict__ cnt, int* __restrict__ rowptr,
                            int* __restrict__ cursor, int N) {
    __shared__ int part[1024];
    int tid = threadIdx.x;
    int chunk = (N + 1023) / 1024;
    int start = tid * chunk;
    int end = min(start + chunk, N);
    int s = 0;
    for (int i = start; i < end; i++) s += cnt[i];
    part[tid] = s;
    __syncthreads();
    for (int off = 1; off < 1024; off <<= 1) {
        int v = (tid >= off) ? part[tid - off] : 0;
        __syncthreads();
        part[tid] += v;
        __syncthreads();
    }
    int run = (tid == 0) ? 0 : part[tid - 1];
    for (int i = start; i < end; i++) {
        rowptr[i] = run;
        cursor[i] = run;
        run += cnt[i];
    }
    if (end == N) rowptr[N] = run;
}

__global__ void bucket_kernel(int* __restrict__ cursor, int* __restrict__ esrc,
                              const void* ei, int E, int N) {
    int i = blockIdx.x * blockDim.x + threadIdx.x;
    if (i >= E) return;
    bool is64 = edges_are_i64(ei, N);
    int s, d;
    if (is64) {
        s = (int)((const long long*)ei)[i];
        d = (int)((const long long*)ei)[E + i];
    } else {
        s = ((const int*)ei)[i];
        d = ((const int*)ei)[E + i];
    }
    int pos = atomicAdd(&cursor[d], 1);
    esrc[pos] = s;
}

// ---------------------------------------------------------------------------
// Fused GIN layer (persistent, warp-specialized):
//   out = relu(relu((x + gather(x)) @ W1 + b1) @ W2 + b2)
// Tile = 64 dst nodes. Warps 0-3 (producers, one per SMSP): gather next tile
// into double-buffered smem A (fp32, XOR-swizzled). Warps 4-7 (consumers, one
// per SMSP): mma1 (tf32) -> h (tf32, warp-private smem) -> mma2 -> STG.
// Named barriers: full[b]=1+b, free[b]=3+b.
//
// Swizzles (conflict-free fragment access):
//   A/h element (r,k):  base + r*128 + (k ^ ((r&7)<<2))
//   W  element (k,n):   base + k*128 + (n ^ ((k&3)<<3))
// ---------------------------------------------------------------------------
#define SMF_BIAS1 0
#define SMF_BIAS2 128
#define SMF_W1    256
#define SMF_W2    (256 + 16384)
#define SMF_A0    (256 + 32768)
#define SMF_A1    (SMF_A0 + 8192)
#define SMF_H     (SMF_A1 + 8192)
#define LAYER_SMEM ((SMF_H + 8192) * 4)          // 230400 B

__global__ void __launch_bounds__(256, 1)
layer_fused(const float* __restrict__ X, const float* __restrict__ W1,
            const float* __restrict__ b1, const float* __restrict__ W2,
            const float* __restrict__ b2, float* __restrict__ OUT,
            const int* __restrict__ rowptr, const int* __restrict__ esrc,
            int N, int ntiles) {
    extern __shared__ float sm[];
    float* bias1 = sm + SMF_BIAS1;
    float* bias2 = sm + SMF_BIAS2;
    uint32_t* W1s = (uint32_t*)(sm + SMF_W1);
    uint32_t* W2s = (uint32_t*)(sm + SMF_W2);

    int tid = threadIdx.x, wid = tid >> 5, lane = tid & 31;
    int g = lane >> 2, t = lane & 3;

    if (tid < 128) bias1[tid] = b1[tid];
    else           bias2[tid - 128] = b2[tid - 128];

    // Stage W1/W2 as tf32, swizzled (once per block)
    for (int i = tid; i < 4096; i += 256) {
        int k = i >> 5;
        int n4 = (i & 31) << 2;
        int swz = (k & 3) << 3;
        float4 v1 = *(const float4*)(W1 + (size_t)k * DDIM + n4);
        float4 v2 = *(const float4*)(W2 + (size_t)k * DDIM + n4);
        W1s[k * 128 + ((n4 + 0) ^ swz)] = f2tf32(v1.x);
        W1s[k * 128 + ((n4 + 1) ^ swz)] = f2tf32(v1.y);
        W1s[k * 128 + ((n4 + 2) ^ swz)] = f2tf32(v1.z);
        W1s[k * 128 + ((n4 + 3) ^ swz)] = f2tf32(v1.w);
        W2s[k * 128 + ((n4 + 0) ^ swz)] = f2tf32(v2.x);
        W2s[k * 128 + ((n4 + 1) ^ swz)] = f2tf32(v2.y);
        W2s[k * 128 + ((n4 + 2) ^ swz)] = f2tf32(v2.z);
        W2s[k * 128 + ((n4 + 3) ^ swz)] = f2tf32(v2.w);
    }
    __syncthreads();

    if (wid < 4) {
        // ---------------- Producer: gather agg rows into A[idx&1] ----------
        int idx = 0;
        for (int tt = blockIdx.x; tt < ntiles; tt += gridDim.x, idx++) {
            float* As = sm + ((idx & 1) ? SMF_A1 : SMF_A0);
            if (idx >= 2) BAR_SYNC(3 + (idx & 1));
            int row0 = tt << 6;
#pragma unroll 1
            for (int i = 0; i < 16; i++) {
                int node = row0 + (wid << 4) + i;
                float4 acc = make_float4(0.f, 0.f, 0.f, 0.f);
                if (node < N) {
                    acc = ((const float4*)(X + (size_t)node * DDIM))[lane];
                    int b = rowptr[node], e = rowptr[node + 1];
                    for (int base = b; base < e; base += 32) {
                        int m = min(32, e - base);
                        int sv = (lane < m) ? esrc[base + lane] : 0;
                        for (int j0 = 0; j0 < m; j0 += 8) {
                            float4 v[8];
#pragma unroll
                            for (int jj = 0; jj < 8; jj++) {
                                int s = __shfl_sync(0xffffffffu, sv, (j0 + jj) & 31);
                                if (j0 + jj < m)
                                    v[jj] = ((const float4*)(X + (size_t)s * DDIM))[lane];
                                else
                                    v[jj] = make_float4(0.f, 0.f, 0.f, 0.f);
                            }
#pragma unroll
                            for (int jj = 0; jj < 8; jj++) {
                                acc.x += v[jj].x; acc.y += v[jj].y;
                                acc.z += v[jj].z; acc.w += v[jj].w;
                            }
                        }
                    }
                }
                int r = (wid << 4) + i;
                int ci = (lane << 2) ^ ((r & 7) << 2);
                *(float4*)(As + r * 128 + ci) = acc;
            }
            BAR_ARRIVE(1 + (idx & 1));
        }
    } else {
        // ---------------- Consumer: mma1 -> h -> mma2 -> STG --------------
        int cw = wid - 4;
        uint32_t* hrow = (uint32_t*)(sm + SMF_H) + (cw << 4) * 128;
        int swz = g << 2;
        int idx = 0;
        for (int tt = blockIdx.x; tt < ntiles; tt += gridDim.x, idx++) {
            const float* As = sm + ((idx & 1) ? SMF_A1 : SMF_A0);
            BAR_SYNC(1 + (idx & 1));
            int row0 = tt << 6;

            // ---- GEMM1: acc = agg @ W1 ----
            float acc[16][4];
#pragma unroll
            for (int nt = 0; nt < 16; nt++)
#pragma unroll
                for (int j = 0; j < 4; j++) acc[nt][j] = 0.f;

            const float* ar0 = As + ((cw << 4) + g) * 128;
            const float* ar1 = ar0 + 8 * 128;
#pragma unroll 4
            for (int ks = 0; ks < 16; ks++) {
                int k0 = (ks << 3) + t;
                uint32_t a[4];
                a[0] = f2tf32(ar0[k0 ^ swz]);
                a[1] = f2tf32(ar1[k0 ^ swz]);
                a[2] = f2tf32(ar0[(k0 + 4) ^ swz]);
                a[3] = f2tf32(ar1[(k0 + 4) ^ swz]);
#pragma unroll
                for (int nt = 0; nt < 16; nt++) {
                    int cb = ((nt << 3) + g) ^ (t << 3);
                    uint32_t b[2];
                    b[0] = W1s[k0 * 128 + cb];
                    b[1] = W1s[(k0 + 4) * 128 + cb];
                    mma_m16n8k8(acc[nt], a, b);
                }
            }
            BAR_ARRIVE(3 + (idx & 1));   // A buffer reusable

            // ---- h = tf32(relu(acc + b1)) into warp-private smem ----
#pragma unroll
            for (int nt = 0; nt < 16; nt++) {
                int c0 = (nt << 3) + (t << 1);
                float b0 = bias1[c0], b1v = bias1[c0 + 1];
                hrow[g * 128 + (c0 ^ swz)]           = f2tf32(fmaxf(acc[nt][0] + b0, 0.f));
                hrow[g * 128 + ((c0 + 1) ^ swz)]     = f2tf32(fmaxf(acc[nt][1] + b1v, 0.f));
                hrow[(g + 8) * 128 + (c0 ^ swz)]     = f2tf32(fmaxf(acc[nt][2] + b0, 0.f));
                hrow[(g + 8) * 128 + ((c0 + 1) ^ swz)] = f2tf32(fmaxf(acc[nt][3] + b1v, 0.f));
            }
            __syncwarp();

            // ---- GEMM2: acc2 = h @ W2 ----
            float acc2[16][4];
#pragma unroll
            for (int nt = 0; nt < 16; nt++)
#pragma unroll
                for (int j = 0; j < 4; j++) acc2[nt][j] = 0.f;

            const uint32_t* hr0 = hrow + g * 128;
            const uint32_t* hr1 = hr0 + 8 * 128;
#pragma unroll 4
            for (int ks = 0; ks < 16; ks++) {
                int k0 = (ks << 3) + t;
                uint32_t a[4];
                a[0] = hr0[k0 ^ swz];
                a[1] = hr1[k0 ^ swz];
                a[2] = hr0[(k0 + 4) ^ swz];
                a[3] = hr1[(k0 + 4) ^ swz];
#pragma unroll
                for (int nt = 0; nt < 16; nt++) {
                    int cb = ((nt << 3) + g) ^ (t << 3);
                    uint32_t b[2];
                    b[0] = W2s[k0 * 128 + cb];
                    b[1] = W2s[(k0 + 4) * 128 + cb];
                    mma_m16n8k8(acc2[nt], a, b);
                }
            }
            __syncwarp();   // done reading hrow before next tile overwrites

            // ---- epilogue: relu(acc2 + b2) -> OUT ----
            int r0 = row0 + (cw << 4) + g;
            int r1 = r0 + 8;
#pragma unroll
            for (int nt = 0; nt < 16; nt++) {
                int c0 = (nt << 3) + (t << 1);
                float b0 = bias2[c0], b1v = bias2[c0 + 1];
                if (r0 < N) {
                    float2 o;
                    o.x = fmaxf(acc2[nt][0] + b0, 0.f);
                    o.y = fmaxf(acc2[nt][1] + b1v, 0.f);
                    *(float2*)(OUT + (size_t)r0 * DDIM + c0) = o;
                }
                if (r1 < N) {
                    float2 o;
                    o.x = fmaxf(acc2[nt][2] + b0, 0.f);
                    o.y = fmaxf(acc2[nt][3] + b1v, 0.f);
                    *(float2*)(OUT + (size_t)r1 * DDIM + c0) = o;
                }
            }
        }
    }
}

// ---------------------------------------------------------------------------
extern "C" void kernel_launch(void* const* d_in, const int* in_sizes, int n_in,
                              void* d_out, int out_size) {
    const float* x  = (const float*)d_in[0];
    const void*  ei = d_in[1];
    const float* W1 = (const float*)d_in[2];
    const float* b1 = (const float*)d_in[3];
    const float* W2 = (const float*)d_in[4];
    const float* b2 = (const float*)d_in[5];

    int N = in_sizes[0] / DDIM;
    int E = in_sizes[1] / 2;
    int L = in_sizes[3] / DDIM;

    float* out = (float*)d_out;

    float *x1, *x2;
    int *cnt, *rowptr, *cursor, *esrc;
    cudaGetSymbolAddress((void**)&x1,     g_x1);
    cudaGetSymbolAddress((void**)&x2,     g_x2);
    cudaGetSymbolAddress((void**)&cnt,    g_cnt);
    cudaGetSymbolAddress((void**)&rowptr, g_rowptr);
    cudaGetSymbolAddress((void**)&cursor, g_cursor);
    cudaGetSymbolAddress((void**)&esrc,   g_esrc);

    static int smem_set = 0;
    if (!smem_set) {
        cudaFuncSetAttribute(layer_fused,
                             cudaFuncAttributeMaxDynamicSharedMemorySize, LAYER_SMEM);
        smem_set = 1;
    }

    // ---- CSR build (once per launch) ----
    zero_cnt_kernel<<<(N + 255) / 256, 256>>>(cnt, N);
    hist_kernel<<<(E + 255) / 256, 256>>>(cnt, ei, E, N);
    scan_kernel<<<1, 1024>>>(cnt, rowptr, cursor, N);
    bucket_kernel<<<(E + 255) / 256, 256>>>(cursor, esrc, ei, E, N);

    int ntiles = (N + 63) / 64;
    int grid = ntiles < 148 ? ntiles : 148;

    const float* cur = x;
    for (int l = 0; l < L; l++) {
        float* dst = (l == L - 1) ? out : ((l & 1) ? x2 : x1);
        layer_fused<<<grid, 256, LAYER_SMEM>>>(
            cur, W1 + (size_t)l * DDIM * DDIM, b1 + (size_t)l * DDIM,
            W2 + (size_t)l * DDIM * DDIM, b2 + (size_t)l * DDIM,
            dst, rowptr, esrc, N, ntiles);
        cur = dst;
    }
}

// round 9
// speedup vs baseline: 2.0565x; 2.0565x over previous
#include <cuda_runtime.h>
#include <cuda_fp16.h>
#include <cstdint>

#define DDIM 128
#define MAXN 50048
#define MAXE 2097152
#define PADB2 132  // Bs row stride (half2 words), rows indexed by k/2
#define PADA 36    // As row stride (floats)

// Scratch (allocation-free: __device__ globals)
__device__ float g_agg[(size_t)MAXN * DDIM];
__device__ float g_h  [(size_t)MAXN * DDIM];
__device__ float g_x  [(size_t)MAXN * DDIM];
__device__ int   g_cnt[MAXN];
__device__ int   g_rowptr[MAXN + 1];
__device__ int   g_cursor[MAXN];
__device__ int   g_esrc[MAXE];

// ---------------------------------------------------------------------------
// Helpers
// ---------------------------------------------------------------------------
__device__ __forceinline__ uint32_t smem_u32(const void* p) {
    uint32_t a;
    asm("{ .reg .u64 t; cvta.to.shared.u64 t, %1; cvt.u32.u64 %0, t; }"
        : "=r"(a) : "l"(p));
    return a;
}
__device__ __forceinline__ void cp_async16(uint32_t dst, const void* src, bool pred) {
    int sz = pred ? 16 : 0;
    asm volatile("cp.async.ca.shared.global [%0], [%1], 16, %2;"
                 :: "r"(dst), "l"(src), "r"(sz));
}
__device__ __forceinline__ void cp_commit() {
    asm volatile("cp.async.commit_group;" ::: "memory");
}
__device__ __forceinline__ uint32_t pack_h2(float lo, float hi) {
    __half2 h = __floats2half2_rn(lo, hi);
    return *(uint32_t*)&h;
}

__device__ __forceinline__ void mma_m16n8k16_f16(float c[4], const uint32_t a[4],
                                                 const uint32_t b[2]) {
    asm volatile(
        "mma.sync.aligned.m16n8k16.row.col.f32.f16.f16.f32 "
        "{%0,%1,%2,%3}, {%4,%5,%6,%7}, {%8,%9}, {%0,%1,%2,%3};\n"
        : "+f"(c[0]), "+f"(c[1]), "+f"(c[2]), "+f"(c[3])
        : "r"(a[0]), "r"(a[1]), "r"(a[2]), "r"(a[3]), "r"(b[0]), "r"(b[1]));
}

// ---------------------------------------------------------------------------
// Edge dtype self-detection (int64 vs int32)
// ---------------------------------------------------------------------------
__device__ __forceinline__ bool edges_are_i64(const void* ei, int N) {
    const long long* e64 = (const long long*)ei;
#pragma unroll
    for (int i = 0; i < 4; i++) {
        long long v = e64[i];
        if (v < 0 || v >= (long long)N) return false;
    }
    return true;
}

__global__ void zero_cnt_kernel(int* cnt, int n) {
    int i = blockIdx.x * blockDim.x + threadIdx.x;
    if (i < n) cnt[i] = 0;
}

__global__ void hist_kernel(int* cnt, const void* ei, int E, int N) {
    int i = blockIdx.x * blockDim.x + threadIdx.x;
    if (i >= E) return;
    bool is64 = edges_are_i64(ei, N);
    int d;
    if (is64) d = (int)((const long long*)ei)[E + i];
    else      d = ((const int*)ei)[E + i];
    atomicAdd(&cnt[d], 1);
}

__global__ void scan_kernel(const int* __restrict__ cnt, int* __restrict__ rowptr,
                            int* __restrict__ cursor, int N) {
    __shared__ int part[1024];
    int tid = threadIdx.x;
    int chunk = (N + 1023) / 1024;
    int start = tid * chunk;
    int end = min(start + chunk, N);
    int s = 0;
    for (int i = start; i < end; i++) s += cnt[i];
    part[tid] = s;
    __syncthreads();
    for (int off = 1; off < 1024; off <<= 1) {
        int v = (tid >= off) ? part[tid - off] : 0;
        __syncthreads();
        part[tid] += v;
        __syncthreads();
    }
    int run = (tid == 0) ? 0 : part[tid - 1];
    for (int i = start; i < end; i++) {
        rowptr[i] = run;
        cursor[i] = run;
        run += cnt[i];
    }
    if (end == N) rowptr[N] = run;
}

__global__ void bucket_kernel(int* __restrict__ cursor, int* __restrict__ esrc,
                              const void* ei, int E, int N) {
    int i = blockIdx.x * blockDim.x + threadIdx.x;
    if (i >= E) return;
    bool is64 = edges_are_i64(ei, N);
    int s, d;
    if (is64) {
        s = (int)((const long long*)ei)[i];
        d = (int)((const long long*)ei)[E + i];
    } else {
        s = ((const int*)ei)[i];
        d = ((const int*)ei)[E + i];
    }
    int pos = atomicAdd(&cursor[d], 1);
    esrc[pos] = s;
}

// ---------------------------------------------------------------------------
// agg[i] = x[i] + sum_{s in in-neighbors(i)} x[s].  One warp per node.
// ---------------------------------------------------------------------------
__global__ void gather_agg_kernel(float* __restrict__ agg, const float* __restrict__ x,
                                  const int* __restrict__ rowptr,
                                  const int* __restrict__ esrc, int N) {
    int node = blockIdx.x * (blockDim.x >> 5) + (threadIdx.x >> 5);
    if (node >= N) return;
    int lane = threadIdx.x & 31;

    float4 acc = ((const float4*)(x + (size_t)node * DDIM))[lane];
    int b = rowptr[node];
    int e = rowptr[node + 1];

    for (int base = b; base < e; base += 32) {
        int m = min(32, e - base);
        int sv = (lane < m) ? esrc[base + lane] : 0;
#pragma unroll 4
        for (int j = 0; j < m; j++) {
            int s = __shfl_sync(0xffffffffu, sv, j);
            float4 v = ((const float4*)(x + (size_t)s * DDIM))[lane];
            acc.x += v.x; acc.y += v.y; acc.z += v.z; acc.w += v.w;
        }
    }
    ((float4*)(agg + (size_t)node * DDIM))[lane] = acc;
}

// ---------------------------------------------------------------------------
// Persistent pipelined FP16 mma.sync GEMM (m16n8k16, fp32 accum):
//   C[M,128] = relu(A[M,128] @ W[128,128] + bias)
// W staged once per block as k-paired half2 (B-fragment native layout).
// A staged fp32 via cp.async 2-buffer ring pipelined across chunk/tile
// boundaries; packed to half2 per-fragment. 8 warps, 4(m)x2(n), 32x64 each.
// ---------------------------------------------------------------------------
#define SM_BIAS  0
#define SM_B     128                             // float-offset of Bs (half2 array)
#define SM_A     (128 + 64 * PADB2)              // Bs: 64 rows x PADB2 half2 (4B each)
#define GEMM_SMEM ((128 + 64 * PADB2 + 2 * 128 * PADA) * 4)

__device__ __forceinline__ void prefetch_chunk(const float* __restrict__ A, int M,
                                               int row0, int c, float* __restrict__ dst,
                                               int tid) {
#pragma unroll
    for (int j = 0; j < 4; j++) {
        int i = tid + j * 256;                   // 0..1023
        int r = i >> 3;
        int cc = (i & 7) << 2;
        uint32_t d = smem_u32(dst + r * PADA + cc);
        const float* src = A + (size_t)(row0 + r) * DDIM + c * 32 + cc;
        cp_async16(d, src, row0 + r < M);
    }
    cp_commit();
}

// One 32-k chunk = 2 fp16 k-steps of 16.
__device__ __forceinline__ void compute_chunk(
    const float* __restrict__ As_c, const uint32_t* __restrict__ Bs, int kbase,
    int mrow, int ncol, int g, int t, float acc[2][8][4]) {
#pragma unroll
    for (int ks = 0; ks < 2; ks++) {
        int kk = ks * 16;
        uint32_t a[2][4];
#pragma unroll
        for (int mt = 0; mt < 2; mt++) {
            const float* r0 = As_c + (mrow + mt * 16 + g) * PADA + kk + 2 * t;
            const float* r1 = r0 + 8 * PADA;
            float2 p0 = *(const float2*)(r0);
            float2 p1 = *(const float2*)(r1);
            float2 p2 = *(const float2*)(r0 + 8);
            float2 p3 = *(const float2*)(r1 + 8);
            a[mt][0] = pack_h2(p0.x, p0.y);
            a[mt][1] = pack_h2(p1.x, p1.y);
            a[mt][2] = pack_h2(p2.x, p2.y);
            a[mt][3] = pack_h2(p3.x, p3.y);
        }
        int k2 = (kbase + kk) >> 1;              // row in Bs (k-pairs)
        uint32_t b[8][2];
#pragma unroll
        for (int nt = 0; nt < 8; nt++) {
            int cc = ncol + nt * 8 + g;
            b[nt][0] = Bs[(k2 + t) * PADB2 + cc];
            b[nt][1] = Bs[(k2 + t + 4) * PADB2 + cc];
        }
#pragma unroll
        for (int mt = 0; mt < 2; mt++)
#pragma unroll
            for (int nt = 0; nt < 8; nt++)
                mma_m16n8k16_f16(acc[mt][nt], a[mt], b[nt]);
    }
}

__global__ void __launch_bounds__(256, 2)
gemm_f16_pipe(const float* __restrict__ A, const float* __restrict__ W,
              const float* __restrict__ bias, float* __restrict__ C,
              int M, int ntiles) {
    extern __shared__ float sm[];
    float* bias_s = sm + SM_BIAS;
    uint32_t* Bs = (uint32_t*)(sm + SM_B);       // half2[k/2][PADB2]
    float* As = sm + SM_A;                       // [2][128][PADA]

    int tid = threadIdx.x;
    int wid = tid >> 5, lane = tid & 31;
    int g = lane >> 2, t = lane & 3;
    int mrow = (wid >> 1) * 32, ncol = (wid & 1) * 64;

    if (tid < 128) bias_s[tid] = bias[tid];
    // Stage W once as k-paired half2: Bs[k2][n] = {W[2k2][n], W[2k2+1][n]}
    for (int i = tid; i < 2048; i += 256) {
        int k2 = i >> 5;
        int n4 = (i & 31) << 2;
        float4 v0 = *(const float4*)(W + (size_t)(2 * k2) * DDIM + n4);
        float4 v1 = *(const float4*)(W + (size_t)(2 * k2 + 1) * DDIM + n4);
        uint32_t* p = &Bs[k2 * PADB2 + n4];
        p[0] = pack_h2(v0.x, v1.x);
        p[1] = pack_h2(v0.y, v1.y);
        p[2] = pack_h2(v0.z, v1.z);
        p[3] = pack_h2(v0.w, v1.w);
    }
    __syncthreads();

    // Continuous chunk pipeline across tiles; one cp.async group in flight.
    int buf = 0;
    if (blockIdx.x < ntiles)
        prefetch_chunk(A, M, blockIdx.x << 7, 0, As, tid);

    for (int tt = blockIdx.x; tt < ntiles; tt += gridDim.x) {
        int row0 = tt << 7;
        float acc[2][8][4];
#pragma unroll
        for (int mt = 0; mt < 2; mt++)
#pragma unroll
            for (int nt = 0; nt < 8; nt++)
#pragma unroll
                for (int j = 0; j < 4; j++) acc[mt][nt][j] = 0.f;

#pragma unroll
        for (int c = 0; c < 4; c++) {
            asm volatile("cp.async.wait_group 0;" ::: "memory");
            __syncthreads();
            // issue next chunk (next tile's chunk 0 when c==3)
            int nc = (c + 1) & 3;
            int ntile = (c == 3) ? tt + (int)gridDim.x : tt;
            if (ntile < ntiles)
                prefetch_chunk(A, M, ntile << 7, nc, As + (buf ^ 1) * 128 * PADA, tid);
            compute_chunk(As + buf * 128 * PADA, Bs, c * 32, mrow, ncol, g, t, acc);
            buf ^= 1;
        }

        // Epilogue: bias + relu (overlaps next tile's chunk-0 load)
#pragma unroll
        for (int nt = 0; nt < 8; nt++) {
            int col = ncol + nt * 8 + t * 2;
            float2 bb = *(const float2*)(bias_s + col);
#pragma unroll
            for (int mt = 0; mt < 2; mt++) {
                int r0 = row0 + mrow + mt * 16 + g;
                int r1 = r0 + 8;
                if (r0 < M) {
                    float2 o;
                    o.x = fmaxf(acc[mt][nt][0] + bb.x, 0.f);
                    o.y = fmaxf(acc[mt][nt][1] + bb.y, 0.f);
                    *(float2*)(C + (size_t)r0 * DDIM + col) = o;
                }
                if (r1 < M) {
                    float2 o;
                    o.x = fmaxf(acc[mt][nt][2] + bb.x, 0.f);
                    o.y = fmaxf(acc[mt][nt][3] + bb.y, 0.f);
                    *(float2*)(C + (size_t)r1 * DDIM + col) = o;
                }
            }
        }
    }
}

// ---------------------------------------------------------------------------
extern "C" void kernel_launch(void* const* d_in, const int* in_sizes, int n_in,
                              void* d_out, int out_size) {
    const float* x  = (const float*)d_in[0];
    const void*  ei = d_in[1];
    const float* W1 = (const float*)d_in[2];
    const float* b1 = (const float*)d_in[3];
    const float* W2 = (const float*)d_in[4];
    const float* b2 = (const float*)d_in[5];

    int N = in_sizes[0] / DDIM;
    int E = in_sizes[1] / 2;
    int L = in_sizes[3] / DDIM;

    float* out = (float*)d_out;

    float *agg, *h, *xb;
    int *cnt, *rowptr, *cursor, *esrc;
    cudaGetSymbolAddress((void**)&agg,    g_agg);
    cudaGetSymbolAddress((void**)&h,      g_h);
    cudaGetSymbolAddress((void**)&xb,     g_x);
    cudaGetSymbolAddress((void**)&cnt,    g_cnt);
    cudaGetSymbolAddress((void**)&rowptr, g_rowptr);
    cudaGetSymbolAddress((void**)&cursor, g_cursor);
    cudaGetSymbolAddress((void**)&esrc,   g_esrc);

    static int smem_set = 0;
    if (!smem_set) {
        cudaFuncSetAttribute(gemm_f16_pipe,
                             cudaFuncAttributeMaxDynamicSharedMemorySize, GEMM_SMEM);
        smem_set = 1;
    }

    // ---- CSR build (once per launch) ----
    zero_cnt_kernel<<<(N + 255) / 256, 256>>>(cnt, N);
    hist_kernel<<<(E + 255) / 256, 256>>>(cnt, ei, E, N);
    scan_kernel<<<1, 1024>>>(cnt, rowptr, cursor, N);
    bucket_kernel<<<(E + 255) / 256, 256>>>(cursor, esrc, ei, E, N);

    const float* cur = x;
    int gather_blocks = (N + 7) / 8;
    int ntiles = (N + 127) / 128;
    int gemm_grid = 2 * 148;
    if (gemm_grid > ntiles) gemm_grid = ntiles;

    for (int l = 0; l < L; l++) {
        gather_agg_kernel<<<gather_blocks, 256>>>(agg, cur, rowptr, esrc, N);
        gemm_f16_pipe<<<gemm_grid, 256, GEMM_SMEM>>>(
            agg, W1 + (size_t)l * DDIM * DDIM, b1 + (size_t)l * DDIM, h, N, ntiles);
        float* dst = (l == L - 1) ? out : xb;
        gemm_f16_pipe<<<gemm_grid, 256, GEMM_SMEM>>>(
            h, W2 + (size_t)l * DDIM * DDIM, b2 + (size_t)l * DDIM, dst, N, ntiles);
        cur = dst;
    }
}

// round 10
// speedup vs baseline: 2.1297x; 1.0356x over previous
#include <cuda_runtime.h>
#include <cuda_fp16.h>
#include <cstdint>

#define DDIM 128
#define MAXN 50048
#define MAXE 2097152
#define PADB2 132   // Bs row stride (half2 words), rows indexed by k/2
#define PADAH 136   // As row stride (halfs) -> conflict-free fragment LDS

// Scratch (allocation-free: __device__ globals). Half buffers alias floats.
__device__ float g_b0[(size_t)MAXN * DDIM / 2];   // xh ping
__device__ float g_b1[(size_t)MAXN * DDIM / 2];   // xh pong
__device__ float g_b2[(size_t)MAXN * DDIM / 2];   // aggh
__device__ float g_b3[(size_t)MAXN * DDIM / 2];   // hh
__device__ int   g_cnt[MAXN];
__device__ int   g_rowptr[MAXN + 1];
__device__ int   g_cursor[MAXN];
__device__ int   g_esrc[MAXE];

// ---------------------------------------------------------------------------
// Helpers
// ---------------------------------------------------------------------------
__device__ __forceinline__ uint32_t smem_u32(const void* p) {
    uint32_t a;
    asm("{ .reg .u64 t; cvta.to.shared.u64 t, %1; cvt.u32.u64 %0, t; }"
        : "=r"(a) : "l"(p));
    return a;
}
__device__ __forceinline__ void cp_async16(uint32_t dst, const void* src, bool pred) {
    int sz = pred ? 16 : 0;
    asm volatile("cp.async.ca.shared.global [%0], [%1], 16, %2;"
                 :: "r"(dst), "l"(src), "r"(sz));
}
__device__ __forceinline__ void cp_commit() {
    asm volatile("cp.async.commit_group;" ::: "memory");
}
__device__ __forceinline__ uint32_t pack_h2(float lo, float hi) {
    __half2 h = __floats2half2_rn(lo, hi);
    return *(uint32_t*)&h;
}
__device__ __forceinline__ void mma_m16n8k16_f16(float c[4], const uint32_t a[4],
                                                 const uint32_t b[2]) {
    asm volatile(
        "mma.sync.aligned.m16n8k16.row.col.f32.f16.f16.f32 "
        "{%0,%1,%2,%3}, {%4,%5,%6,%7}, {%8,%9}, {%0,%1,%2,%3};\n"
        : "+f"(c[0]), "+f"(c[1]), "+f"(c[2]), "+f"(c[3])
        : "r"(a[0]), "r"(a[1]), "r"(a[2]), "r"(a[3]), "r"(b[0]), "r"(b[1]));
}
// Overloaded epilogue store (2 consecutive cols)
__device__ __forceinline__ void store2(float* C, size_t idx, float x, float y) {
    float2 o; o.x = x; o.y = y;
    *(float2*)(C + idx) = o;
}
__device__ __forceinline__ void store2(__half* C, size_t idx, float x, float y) {
    *(uint32_t*)(C + idx) = pack_h2(x, y);
}

// ---------------------------------------------------------------------------
// Edge dtype self-detection (int64 vs int32)
// ---------------------------------------------------------------------------
__device__ __forceinline__ bool edges_are_i64(const void* ei, int N) {
    const long long* e64 = (const long long*)ei;
#pragma unroll
    for (int i = 0; i < 4; i++) {
        long long v = e64[i];
        if (v < 0 || v >= (long long)N) return false;
    }
    return true;
}

__global__ void zero_cnt_kernel(int* cnt, int n) {
    int i = blockIdx.x * blockDim.x + threadIdx.x;
    if (i < n) cnt[i] = 0;
}

__global__ void hist_kernel(int* cnt, const void* ei, int E, int N) {
    int i = blockIdx.x * blockDim.x + threadIdx.x;
    if (i >= E) return;
    bool is64 = edges_are_i64(ei, N);
    int d;
    if (is64) d = (int)((const long long*)ei)[E + i];
    else      d = ((const int*)ei)[E + i];
    atomicAdd(&cnt[d], 1);
}

__global__ void scan_kernel(const int* __restrict__ cnt, int* __restrict__ rowptr,
                            int* __restrict__ cursor, int N) {
    __shared__ int part[1024];
    int tid = threadIdx.x;
    int chunk = (N + 1023) / 1024;
    int start = tid * chunk;
    int end = min(start + chunk, N);
    int s = 0;
    for (int i = start; i < end; i++) s += cnt[i];
    part[tid] = s;
    __syncthreads();
    for (int off = 1; off < 1024; off <<= 1) {
        int v = (tid >= off) ? part[tid - off] : 0;
        __syncthreads();
        part[tid] += v;
        __syncthreads();
    }
    int run = (tid == 0) ? 0 : part[tid - 1];
    for (int i = start; i < end; i++) {
        rowptr[i] = run;
        cursor[i] = run;
        run += cnt[i];
    }
    if (end == N) rowptr[N] = run;
}

__global__ void bucket_kernel(int* __restrict__ cursor, int* __restrict__ esrc,
                              const void* ei, int E, int N) {
    int i = blockIdx.x * blockDim.x + threadIdx.x;
    if (i >= E) return;
    bool is64 = edges_are_i64(ei, N);
    int s, d;
    if (is64) {
        s = (int)((const long long*)ei)[i];
        d = (int)((const long long*)ei)[E + i];
    } else {
        s = ((const int*)ei)[i];
        d = ((const int*)ei)[E + i];
    }
    int pos = atomicAdd(&cursor[d], 1);
    esrc[pos] = s;
}

// ---------------------------------------------------------------------------
// x (fp32) -> xh (fp16)
// ---------------------------------------------------------------------------
__global__ void cvt_f32_f16(__half* __restrict__ dst, const float* __restrict__ src,
                            int n4) {
    int i = blockIdx.x * blockDim.x + threadIdx.x;
    if (i >= n4) return;
    float4 v = ((const float4*)src)[i];
    uint2 o;
    o.x = pack_h2(v.x, v.y);
    o.y = pack_h2(v.z, v.w);
    ((uint2*)dst)[i] = o;
}

// ---------------------------------------------------------------------------
// aggh[i] = fp16( x[i] + sum_{s in in-nb(i)} x[s] )  (fp32 accum), x fp16.
// One warp per node; lane handles 4 cols (uint2 = 4 halfs).
// ---------------------------------------------------------------------------
__global__ void gather_agg_f16(__half* __restrict__ agg, const __half* __restrict__ x,
                               const int* __restrict__ rowptr,
                               const int* __restrict__ esrc, int N) {
    int node = blockIdx.x * (blockDim.x >> 5) + (threadIdx.x >> 5);
    if (node >= N) return;
    int lane = threadIdx.x & 31;

    float acc0, acc1, acc2, acc3;
    {
        uint2 u = ((const uint2*)(x + (size_t)node * DDIM))[lane];
        float2 p0 = __half22float2(*(__half2*)&u.x);
        float2 p1 = __half22float2(*(__half2*)&u.y);
        acc0 = p0.x; acc1 = p0.y; acc2 = p1.x; acc3 = p1.y;
    }
    int b = rowptr[node];
    int e = rowptr[node + 1];

    for (int base = b; base < e; base += 32) {
        int m = min(32, e - base);
        int sv = (lane < m) ? esrc[base + lane] : 0;
        for (int j0 = 0; j0 < m; j0 += 8) {
            uint2 v[8];
#pragma unroll
            for (int jj = 0; jj < 8; jj++) {
                int s = __shfl_sync(0xffffffffu, sv, (j0 + jj) & 31);
                v[jj] = (j0 + jj < m) ? ((const uint2*)(x + (size_t)s * DDIM))[lane]
                                      : make_uint2(0u, 0u);
            }
#pragma unroll
            for (int jj = 0; jj < 8; jj++) {
                float2 p0 = __half22float2(*(__half2*)&v[jj].x);
                float2 p1 = __half22float2(*(__half2*)&v[jj].y);
                acc0 += p0.x; acc1 += p0.y; acc2 += p1.x; acc3 += p1.y;
            }
        }
    }
    uint2 o;
    o.x = pack_h2(acc0, acc1);
    o.y = pack_h2(acc2, acc3);
    ((uint2*)(agg + (size_t)node * DDIM))[lane] = o;
}

// ---------------------------------------------------------------------------
// Persistent pipelined FP16 GEMM (m16n8k16, fp32 accum), fp16 A in gmem:
//   C[M,128] = relu(A[M,128] @ W[128,128] + bias)   (C fp16 or fp32)
// W (fp32 gmem) staged once as k-paired half2. A staged via cp.async 2-buffer
// ring pipelined across chunk/tile boundaries. 8 warps, 4(m)x2(n).
// ---------------------------------------------------------------------------
#define SMB_BIAS  0
#define SMB_B     512                             // bytes
#define SMB_A     (512 + 64 * PADB2 * 4)          // Bs: 64 x PADB2 half2
#define GEMM_SMEM (SMB_A + 2 * 128 * PADAH * 2)   // + 2 A buffers (half)

__device__ __forceinline__ void prefetch_chunk(const __half* __restrict__ A, int M,
                                               int row0, int c, __half* __restrict__ dst,
                                               int tid) {
#pragma unroll
    for (int j = 0; j < 2; j++) {
        int i = tid + j * 256;                   // 0..511
        int r = i >> 2;                          // 0..127
        int seg = (i & 3) << 3;                  // 0,8,16,24 halfs
        uint32_t d = smem_u32(dst + r * PADAH + c * 32 + seg);
        const __half* src = A + (size_t)(row0 + r) * DDIM + c * 32 + seg;
        cp_async16(d, src, row0 + r < M);
    }
    cp_commit();
}

// One 32-k chunk = 2 fp16 k-steps of 16. As_c points at chunk base (row stride PADAH).
__device__ __forceinline__ void compute_chunk(
    const __half* __restrict__ As_c, const uint32_t* __restrict__ Bs, int kbase,
    int mrow, int ncol, int g, int t, float acc[2][8][4]) {
#pragma unroll
    for (int ks = 0; ks < 2; ks++) {
        int kk = ks * 16;
        uint32_t a[2][4];
#pragma unroll
        for (int mt = 0; mt < 2; mt++) {
            const __half* r0 = As_c + (mrow + mt * 16 + g) * PADAH + kk + 2 * t;
            const __half* r1 = r0 + 8 * PADAH;
            a[mt][0] = *(const uint32_t*)(r0);
            a[mt][1] = *(const uint32_t*)(r1);
            a[mt][2] = *(const uint32_t*)(r0 + 8);
            a[mt][3] = *(const uint32_t*)(r1 + 8);
        }
        int k2 = (kbase + kk) >> 1;
        uint32_t b[8][2];
#pragma unroll
        for (int nt = 0; nt < 8; nt++) {
            int cc = ncol + nt * 8 + g;
            b[nt][0] = Bs[(k2 + t) * PADB2 + cc];
            b[nt][1] = Bs[(k2 + t + 4) * PADB2 + cc];
        }
#pragma unroll
        for (int mt = 0; mt < 2; mt++)
#pragma unroll
            for (int nt = 0; nt < 8; nt++)
                mma_m16n8k16_f16(acc[mt][nt], a[mt], b[nt]);
    }
}

template <typename OutT>
__global__ void __launch_bounds__(256, 2)
gemm_f16_pipe(const __half* __restrict__ A, const float* __restrict__ W,
              const float* __restrict__ bias, OutT* __restrict__ C,
              int M, int ntiles) {
    extern __shared__ char smraw[];
    float* bias_s = (float*)(smraw + SMB_BIAS);
    uint32_t* Bs = (uint32_t*)(smraw + SMB_B);
    __half* As = (__half*)(smraw + SMB_A);       // [2][128][PADAH]

    int tid = threadIdx.x;
    int wid = tid >> 5, lane = tid & 31;
    int g = lane >> 2, t = lane & 3;
    int mrow = (wid >> 1) * 32, ncol = (wid & 1) * 64;

    if (tid < 128) bias_s[tid] = bias[tid];
    // Stage W once as k-paired half2: Bs[k2][n] = {W[2k2][n], W[2k2+1][n]}
    for (int i = tid; i < 2048; i += 256) {
        int k2 = i >> 5;
        int n4 = (i & 31) << 2;
        float4 v0 = *(const float4*)(W + (size_t)(2 * k2) * DDIM + n4);
        float4 v1 = *(const float4*)(W + (size_t)(2 * k2 + 1) * DDIM + n4);
        uint32_t* p = &Bs[k2 * PADB2 + n4];
        p[0] = pack_h2(v0.x, v1.x);
        p[1] = pack_h2(v0.y, v1.y);
        p[2] = pack_h2(v0.z, v1.z);
        p[3] = pack_h2(v0.w, v1.w);
    }
    __syncthreads();

    int buf = 0;
    if (blockIdx.x < ntiles)
        prefetch_chunk(A, M, blockIdx.x << 7, 0, As, tid);

    for (int tt = blockIdx.x; tt < ntiles; tt += gridDim.x) {
        int row0 = tt << 7;
        float acc[2][8][4];
#pragma unroll
        for (int mt = 0; mt < 2; mt++)
#pragma unroll
            for (int nt = 0; nt < 8; nt++)
#pragma unroll
                for (int j = 0; j < 4; j++) acc[mt][nt][j] = 0.f;

#pragma unroll
        for (int c = 0; c < 4; c++) {
            asm volatile("cp.async.wait_group 0;" ::: "memory");
            __syncthreads();
            int nc = (c + 1) & 3;
            int ntile = (c == 3) ? tt + (int)gridDim.x : tt;
            if (ntile < ntiles)
                prefetch_chunk(A, M, ntile << 7, nc, As + (buf ^ 1) * 128 * PADAH, tid);
            compute_chunk(As + buf * 128 * PADAH + c * 32, Bs, c * 32,
                          mrow, ncol, g, t, acc);
            buf ^= 1;
        }

        // Epilogue: bias + relu
#pragma unroll
        for (int nt = 0; nt < 8; nt++) {
            int col = ncol + nt * 8 + t * 2;
            float2 bb = *(const float2*)(bias_s + col);
#pragma unroll
            for (int mt = 0; mt < 2; mt++) {
                int r0 = row0 + mrow + mt * 16 + g;
                int r1 = r0 + 8;
                if (r0 < M)
                    store2(C, (size_t)r0 * DDIM + col,
                           fmaxf(acc[mt][nt][0] + bb.x, 0.f),
                           fmaxf(acc[mt][nt][1] + bb.y, 0.f));
                if (r1 < M)
                    store2(C, (size_t)r1 * DDIM + col,
                           fmaxf(acc[mt][nt][2] + bb.x, 0.f),
                           fmaxf(acc[mt][nt][3] + bb.y, 0.f));
            }
        }
    }
}

// ---------------------------------------------------------------------------
extern "C" void kernel_launch(void* const* d_in, const int* in_sizes, int n_in,
                              void* d_out, int out_size) {
    const float* x  = (const float*)d_in[0];
    const void*  ei = d_in[1];
    const float* W1 = (const float*)d_in[2];
    const float* b1 = (const float*)d_in[3];
    const float* W2 = (const float*)d_in[4];
    const float* b2 = (const float*)d_in[5];

    int N = in_sizes[0] / DDIM;
    int E = in_sizes[1] / 2;
    int L = in_sizes[3] / DDIM;

    float* out = (float*)d_out;

    float *fb0, *fb1, *fb2, *fb3;
    int *cnt, *rowptr, *cursor, *esrc;
    cudaGetSymbolAddress((void**)&fb0,    g_b0);
    cudaGetSymbolAddress((void**)&fb1,    g_b1);
    cudaGetSymbolAddress((void**)&fb2,    g_b2);
    cudaGetSymbolAddress((void**)&fb3,    g_b3);
    cudaGetSymbolAddress((void**)&cnt,    g_cnt);
    cudaGetSymbolAddress((void**)&rowptr, g_rowptr);
    cudaGetSymbolAddress((void**)&cursor, g_cursor);
    cudaGetSymbolAddress((void**)&esrc,   g_esrc);

    __half* xh0  = (__half*)fb0;
    __half* xh1  = (__half*)fb1;
    __half* aggh = (__half*)fb2;
    __half* hh   = (__half*)fb3;

    static int smem_set = 0;
    if (!smem_set) {
        cudaFuncSetAttribute(gemm_f16_pipe<__half>,
                             cudaFuncAttributeMaxDynamicSharedMemorySize, GEMM_SMEM);
        cudaFuncSetAttribute(gemm_f16_pipe<float>,
                             cudaFuncAttributeMaxDynamicSharedMemorySize, GEMM_SMEM);
        smem_set = 1;
    }

    // ---- CSR build (once per launch) ----
    zero_cnt_kernel<<<(N + 255) / 256, 256>>>(cnt, N);
    hist_kernel<<<(E + 255) / 256, 256>>>(cnt, ei, E, N);
    scan_kernel<<<1, 1024>>>(cnt, rowptr, cursor, N);
    bucket_kernel<<<(E + 255) / 256, 256>>>(cursor, esrc, ei, E, N);

    int n4 = N * DDIM / 4;
    cvt_f32_f16<<<(n4 + 255) / 256, 256>>>(xh0, x, n4);

    int gather_blocks = (N + 7) / 8;
    int ntiles = (N + 127) / 128;
    int gemm_grid = 2 * 148;
    if (gemm_grid > ntiles) gemm_grid = ntiles;

    const __half* cur = xh0;
    for (int l = 0; l < L; l++) {
        gather_agg_f16<<<gather_blocks, 256>>>(aggh, cur, rowptr, esrc, N);
        gemm_f16_pipe<__half><<<gemm_grid, 256, GEMM_SMEM>>>(
            aggh, W1 + (size_t)l * DDIM * DDIM, b1 + (size_t)l * DDIM, hh, N, ntiles);
        if (l == L - 1) {
            gemm_f16_pipe<float><<<gemm_grid, 256, GEMM_SMEM>>>(
                hh, W2 + (size_t)l * DDIM * DDIM, b2 + (size_t)l * DDIM, out, N, ntiles);
        } else {
            __half* dst = (l & 1) ? xh0 : xh1;
            gemm_f16_pipe<__half><<<gemm_grid, 256, GEMM_SMEM>>>(
                hh, W2 + (size_t)l * DDIM * DDIM, b2 + (size_t)l * DDIM, dst, N, ntiles);
            cur = dst;
        }
    }
}